// round 15
// baseline (speedup 1.0000x reference)
#include <cuda_runtime.h>
#include <math_constants.h>

#define B_ROWS   131072
#define D_EMB    256
#define QSIZE    128
#define TM       64
#define TILES_M  (B_ROWS / TM)   // 2048
#define MARGIN   1.5f

// ---------------- device scratch (static) ----------------
__device__ int    g_counts[4];
__device__ int    g_buckets[4 * B_ROWS];
__device__ float  g_enorm[512];
__device__ float  g_rowloss[B_ROWS];
__device__ double g_bsum[256];

// ---------------- small kernels ----------------
__global__ void reset_kernel() {
    if (threadIdx.x < 4) g_counts[threadIdx.x] = 0;
}
__global__ void classify_kernel(const int* __restrict__ node_type) {
    __shared__ int s_cnt[4];
    __shared__ int s_base[4];
    int tid = threadIdx.x;
    int i = blockIdx.x * blockDim.x + tid;
    if (tid < 4) s_cnt[tid] = 0;
    __syncthreads();
    int t = node_type[i];
    int g = (t == 5) ? 0 : (t == 6) ? 1 : (t == 7) ? 2 : 3;
    int p = atomicAdd(&s_cnt[g], 1);
    __syncthreads();
    if (tid < 4) s_base[tid] = atomicAdd(&g_counts[tid], s_cnt[tid]);
    __syncthreads();
    g_buckets[g * B_ROWS + s_base[g] + p] = i;
}
__global__ void enorm_kernel(const float* __restrict__ cb) {
    int code = blockIdx.x * 8 + (threadIdx.x >> 5);
    int lane = threadIdx.x & 31;
    const float* row = cb + (size_t)code * D_EMB;
    float s = 0.f;
    #pragma unroll
    for (int j = 0; j < 8; ++j)
        s = fmaf(row[lane + 32 * j], row[lane + 32 * j], s);
    #pragma unroll
    for (int o = 16; o; o >>= 1) s += __shfl_xor_sync(0xffffffffu, s, o);
    if (lane == 0) g_enorm[code] = s;
}

// ---------------- PTX helpers ----------------
__device__ __forceinline__ unsigned smem_u32(const void* p) {
    unsigned a;
    asm("{ .reg .u64 t; cvta.to.shared.u64 t, %1; cvt.u32.u64 %0, t; }"
        : "=r"(a) : "l"(p));
    return a;
}
__device__ __forceinline__ void cp16(unsigned saddr, const void* gaddr) {
    asm volatile("cp.async.cg.shared.global [%0], [%1], 16;"
                 :: "r"(saddr), "l"(gaddr) : "memory");
}
__device__ __forceinline__ void cp_arrive(unsigned mbar) {
    asm volatile("cp.async.mbarrier.arrive.noinc.shared::cta.b64 [%0];"
                 :: "r"(mbar) : "memory");
}
__device__ __forceinline__ void mbar_init(unsigned a, unsigned c) {
    asm volatile("mbarrier.init.shared.b64 [%0], %1;" :: "r"(a), "r"(c) : "memory");
}
__device__ __forceinline__ void mbar_arrive(unsigned a) {
    asm volatile("mbarrier.arrive.shared.b64 _, [%0];" :: "r"(a) : "memory");
}
__device__ __forceinline__ void mbar_wait(unsigned a, unsigned parity) {
    asm volatile(
        "{\n\t.reg .pred P;\n\t"
        "WL_%=:\n\t"
        "mbarrier.try_wait.parity.acquire.cta.shared::cta.b64 P, [%0], %1, 0x989680;\n\t"
        "@P bra.uni WD_%=;\n\t"
        "bra.uni WL_%=;\n\t"
        "WD_%=:\n\t}"
        :: "r"(a), "r"(parity) : "memory");
}
__device__ __forceinline__ void ldsm4(unsigned& r0, unsigned& r1,
                                      unsigned& r2, unsigned& r3, unsigned addr) {
    asm volatile("ldmatrix.sync.aligned.m8n8.x4.shared.b16 {%0,%1,%2,%3}, [%4];"
                 : "=r"(r0), "=r"(r1), "=r"(r2), "=r"(r3) : "r"(addr));
}
__device__ __forceinline__ void mma_tf32(float* d, const unsigned* a,
                                         const unsigned* b) {
    asm volatile(
        "mma.sync.aligned.m16n8k8.row.col.f32.tf32.tf32.f32 "
        "{%0,%1,%2,%3}, {%4,%5,%6,%7}, {%8,%9}, {%0,%1,%2,%3};"
        : "+f"(d[0]), "+f"(d[1]), "+f"(d[2]), "+f"(d[3])
        : "r"(a[0]), "r"(a[1]), "r"(a[2]), "r"(a[3]), "r"(b[0]), "r"(b[1]));
}

// ---------------- smem layout ----------------
#define CHUNK_K   16
#define NCHUNK    16
#define NSTAGE    4
#define ROWF      20                       // 80B row stride: LDSM conflict-free
#define TA_BYTES  (TM * ROWF * 4)          // 5120
#define TB_BYTES  (128 * ROWF * 4)         // 10240
#define BUF_BYTES (TA_BYTES + TB_BYTES)    // 15360
#define OFF_BAR   (NSTAGE * BUF_BYTES)     // 61440: full[4] then empty[4]
#define OFF_ROWS  (OFF_BAR + 64)           // 64 int
#define OFF_EN    (OFF_ROWS + 256)         // 128 float
#define OFF_SEL   (OFF_EN + 512)           // 64 int
#define OFF_NC    (OFF_SEL + 256)          // 64 int
#define OFF_CAND  (OFF_NC + 256)           // 64*8 int
#define OFF_PMIN  (OFF_CAND + 2048)        // 128 float
#define OFF_PCOL  (OFF_PMIN + 512)         // 128 int
#define OFF_RMIN  (OFF_PCOL + 512)         // 64 float
#define OFF_WORK  (OFF_RMIN + 256)         // 64 int + counter
#define SMEM_DYN  (OFF_WORK + 272)         // ~66.7 KB -> 3 CTAs/SM

// ---------------- main kernel ----------------
__global__ void __launch_bounds__(256, 3) vq_mma_kernel(
    const float* __restrict__ z, const float* __restrict__ cb,
    float* __restrict__ out)
{
    extern __shared__ char sm[];
    const int g   = blockIdx.y;
    const int tid = threadIdx.x;
    const int cnt   = g_counts[g];
    const int start = blockIdx.x * TM;
    if (start >= cnt) return;

    int*   s_rows = (int*)  (sm + OFF_ROWS);
    float* s_en   = (float*)(sm + OFF_EN);
    int*   s_sel  = (int*)  (sm + OFF_SEL);
    int*   s_nc   = (int*)  (sm + OFF_NC);
    int*   s_cand = (int*)  (sm + OFF_CAND);
    float* s_pmin = (float*)(sm + OFF_PMIN);
    int*   s_pcol = (int*)  (sm + OFF_PCOL);
    float* s_rmin = (float*)(sm + OFF_RMIN);
    int*   s_work = (int*)  (sm + OFF_WORK);
    int*   s_nwork = s_work + 64;

    const unsigned sb = smem_u32(sm);

    if (tid < TM) {
        int r = (start + tid < cnt) ? g_buckets[g * B_ROWS + start + tid] : -1;
        s_rows[tid] = r;
        s_nc[tid] = 0;
    }
    if (tid >= 128 && tid < 256) s_en[tid - 128] = g_enorm[g * QSIZE + tid - 128];
    if (tid == 0) {
        #pragma unroll
        for (int s = 0; s < NSTAGE; ++s) {
            mbar_init(sb + OFF_BAR + s * 8, 256);       // full: 256 cp-arrives
            mbar_init(sb + OFF_BAR + 32 + s * 8, 8);    // empty: 8 warp arrives
        }
        *s_nwork = 0;
    }
    __syncthreads();

    // ---- loader mapping: per chunk A = 1 seg/thread, B = 2 segs/thread ----
    const float* zsrc;  unsigned adst;
    const float* esrc0; unsigned bdst0;
    const float* esrc1; unsigned bdst1;
    {
        int row = tid >> 2, cs = tid & 3;
        int r = s_rows[row];
        zsrc = z + (size_t)(r < 0 ? 0 : r) * D_EMB + cs * 4;
        adst = (unsigned)(row * ROWF + cs * 4) * 4;
        int brow0 = tid >> 2,          bcs0 = tid & 3;
        int brow1 = (tid + 256) >> 2,  bcs1 = tid & 3;
        esrc0 = cb + (size_t)(g * QSIZE + brow0) * D_EMB + bcs0 * 4;
        esrc1 = cb + (size_t)(g * QSIZE + brow1) * D_EMB + bcs1 * 4;
        bdst0 = (unsigned)TA_BYTES + (unsigned)(brow0 * ROWF + bcs0 * 4) * 4;
        bdst1 = (unsigned)TA_BYTES + (unsigned)(brow1 * ROWF + bcs1 * 4) * 4;
    }

    // warp tiling: 4 warp-rows x 2 warp-cols; warp tile = 16 rows x 64 cols
    const int w = tid >> 5, lane = tid & 31;
    const int gq = lane >> 2, t = lane & 3;
    const int wm = w >> 1, wn = w & 1;
    const int R0 = wm * 16, CW = wn * 64;

    const int g8 = lane >> 3, rw = lane & 7;
    const unsigned aOff =
        (unsigned)((R0 + (g8 & 1) * 8 + rw) * ROWF + (g8 >> 1) * 4) * 4;
    unsigned bOff[4];
    #pragma unroll
    for (int p = 0; p < 4; ++p)
        bOff[p] = (unsigned)TA_BYTES +
            (unsigned)((CW + (2 * p + (g8 >> 1)) * 8 + rw) * ROWF + (g8 & 1) * 4) * 4;

    float acc[8][4];
    #pragma unroll
    for (int nf = 0; nf < 8; ++nf)
        #pragma unroll
        for (int q = 0; q < 4; ++q) acc[nf][q] = 0.f;

    // prologue: fill all 4 stages
    #pragma unroll
    for (int c0 = 0; c0 < NSTAGE; ++c0) {
        unsigned buf = sb + c0 * BUF_BYTES;
        cp16(buf + adst,  zsrc  + c0 * CHUNK_K);
        cp16(buf + bdst0, esrc0 + c0 * CHUNK_K);
        cp16(buf + bdst1, esrc1 + c0 * CHUNK_K);
        cp_arrive(sb + OFF_BAR + c0 * 8);
    }

    #pragma unroll 1
    for (int c = 0; c < NCHUNK; ++c) {
        const int s = c & 3, gen = c >> 2;
        mbar_wait(sb + OFF_BAR + s * 8, gen & 1);

        const unsigned bufb = sb + s * BUF_BYTES;
        #pragma unroll
        for (int ks = 0; ks < 2; ++ks) {
            unsigned a[4];
            ldsm4(a[0], a[1], a[2], a[3], bufb + aOff + ks * 32);
            unsigned b[8][2];
            #pragma unroll
            for (int p = 0; p < 4; ++p)
                ldsm4(b[2 * p][0], b[2 * p][1], b[2 * p + 1][0], b[2 * p + 1][1],
                      bufb + bOff[p] + ks * 32);
            #pragma unroll
            for (int nf = 0; nf < 8; ++nf)
                mma_tf32(acc[nf], a, b[nf]);
        }
        if (lane == 0) mbar_arrive(sb + OFF_BAR + 32 + s * 8);

        const int cn = c + NSTAGE;
        if (cn < NCHUNK) {
            mbar_wait(sb + OFF_BAR + 32 + s * 8, gen & 1);
            unsigned buf = sb + s * BUF_BYTES;
            cp16(buf + adst,  zsrc  + cn * CHUNK_K);
            cp16(buf + bdst0, esrc0 + cn * CHUNK_K);
            cp16(buf + bdst1, esrc1 + cn * CHUNK_K);
            cp_arrive(sb + OFF_BAR + s * 8);
        }
    }
    __syncthreads();

    // ---- per-warp partial argmin (score = en - 2*dot) ----
    #pragma unroll
    for (int h = 0; h < 2; ++h) {
        const int row = R0 + gq + h * 8;
        float v = CUDART_INF_F;  int cbest = 0x7fffffff;
        #pragma unroll
        for (int nf = 0; nf < 8; ++nf) {
            #pragma unroll
            for (int q = 0; q < 2; ++q) {
                int col = CW + nf * 8 + 2 * t + q;
                float s = fmaf(-2.f, acc[nf][h * 2 + q], s_en[col]);
                if (s < v || (s == v && col < cbest)) { v = s; cbest = col; }
            }
        }
        #pragma unroll
        for (int off = 1; off < 4; off <<= 1) {
            float v2 = __shfl_xor_sync(0xffffffffu, v, off);
            int   c2 = __shfl_xor_sync(0xffffffffu, cbest, off);
            if (v2 < v || (v2 == v && c2 < cbest)) { v = v2; cbest = c2; }
        }
        if (t == 0) {
            s_pmin[row * 2 + wn] = v;
            s_pcol[row * 2 + wn] = cbest;
        }
    }
    __syncthreads();

    if (tid < TM) {
        float v0 = s_pmin[tid * 2], v1 = s_pmin[tid * 2 + 1];
        int   c0 = s_pcol[tid * 2], c1 = s_pcol[tid * 2 + 1];
        bool take1 = (v1 < v0) || (v1 == v0 && c1 < c0);
        s_rmin[tid] = take1 ? v1 : v0;
        s_sel[tid]  = take1 ? c1 : c0;
    }
    __syncthreads();

    // ---- candidate collection within MARGIN of row min ----
    #pragma unroll
    for (int h = 0; h < 2; ++h) {
        const int row = R0 + gq + h * 8;
        const float thr = s_rmin[row] + MARGIN;
        #pragma unroll
        for (int nf = 0; nf < 8; ++nf) {
            #pragma unroll
            for (int q = 0; q < 2; ++q) {
                int col = CW + nf * 8 + 2 * t + q;
                float s = fmaf(-2.f, acc[nf][h * 2 + q], s_en[col]);
                if (s <= thr) {
                    int p = atomicAdd(&s_nc[row], 1);
                    if (p < 8) s_cand[row * 8 + p] = col;
                }
            }
        }
    }
    __syncthreads();

    // worklist of ambiguous rows
    if (tid < TM) {
        if (s_rows[tid] >= 0 && s_nc[tid] > 1) {
            int p = atomicAdd(s_nwork, 1);
            s_work[p] = tid;
        }
    }
    __syncthreads();

    // pooled exact fp32 rescue: 8 warps strip-mine the worklist
    const int nwork = *s_nwork;
    for (int wi = w; wi < nwork; wi += 8) {
        const int m = s_work[wi];
        const int nc = s_nc[m];
        const int r  = s_rows[m];
        const float* zr = z + (size_t)r * D_EMB;
        float zn = 0.f;
        #pragma unroll
        for (int j = 0; j < 8; ++j)
            zn = fmaf(zr[lane + 32 * j], zr[lane + 32 * j], zn);
        #pragma unroll
        for (int off = 16; off; off >>= 1)
            zn += __shfl_xor_sync(0xffffffffu, zn, off);
        float bestv = CUDART_INF_F;  int bestc = 0x7fffffff;
        int nit = (nc <= 8) ? nc : QSIZE;
        for (int i = 0; i < nit; ++i) {
            int col = (nc <= 8) ? s_cand[m * 8 + i] : i;
            const float* er = cb + (size_t)(g * QSIZE + col) * D_EMB;
            float p = 0.f;
            #pragma unroll
            for (int j = 0; j < 8; ++j)
                p = fmaf(zr[lane + 32 * j], er[lane + 32 * j], p);
            #pragma unroll
            for (int off = 16; off; off >>= 1)
                p += __shfl_xor_sync(0xffffffffu, p, off);
            float sc = fmaf(-2.f, p, zn + s_en[col]);
            if (sc < bestv || (sc == bestv && col < bestc)) { bestv = sc; bestc = col; }
        }
        if (lane == 0) s_sel[m] = bestc;
    }
    __syncthreads();

    // ---- fused epilogue: idx write + st = z + (q - z) + per-row loss ----
    if (tid < TM) {
        int r = s_rows[tid];
        if (r >= 0) out[2 + r] = (float)(g * QSIZE + s_sel[tid]);
    }
    {
        const int m = tid >> 2, h = tid & 3;          // 4 threads per row
        const int r = s_rows[m];
        float lsum = 0.f;
        if (r >= 0) {
            const int code = g * QSIZE + s_sel[m];
            const float* zr = z  + (size_t)r    * D_EMB + h * 64;
            const float* qr = cb + (size_t)code * D_EMB + h * 64;
            float* so = out + 2 + B_ROWS + (size_t)r * D_EMB + h * 64;
            #pragma unroll 4
            for (int cc = 0; cc < 64; cc += 4) {
                float4 zv = *(const float4*)(zr + cc);
                float4 qv = *(const float4*)(qr + cc);
                float dx = qv.x - zv.x, dy = qv.y - zv.y;
                float dz = qv.z - zv.z, dw = qv.w - zv.w;
                *(float2*)(so + cc)     = make_float2(zv.x + dx, zv.y + dy);
                *(float2*)(so + cc + 2) = make_float2(zv.z + dz, zv.w + dw);
                lsum += dx * dx; lsum += dy * dy; lsum += dz * dz; lsum += dw * dw;
            }
        }
        // combine the 4 quarter-row sums (threads 4m..4m+3 share a warp)
        lsum += __shfl_down_sync(0xffffffffu, lsum, 2);
        lsum += __shfl_down_sync(0xffffffffu, lsum, 1);
        if (h == 0 && r >= 0) g_rowloss[r] = lsum;
    }
}

// ---------------- loss reduction ----------------
__global__ void rowloss_reduce_kernel() {
    __shared__ double sd[256];
    int base = blockIdx.x * 512;
    double s = (double)g_rowloss[base + threadIdx.x]
             + (double)g_rowloss[base + 256 + threadIdx.x];
    sd[threadIdx.x] = s;
    __syncthreads();
    #pragma unroll
    for (int o = 128; o; o >>= 1) {
        if (threadIdx.x < o) sd[threadIdx.x] += sd[threadIdx.x + o];
        __syncthreads();
    }
    if (threadIdx.x == 0) g_bsum[blockIdx.x] = sd[0];
}

__global__ void finalize_kernel(float* __restrict__ out) {
    __shared__ double sd[256];
    sd[threadIdx.x] = g_bsum[threadIdx.x];
    __syncthreads();
    #pragma unroll
    for (int o = 128; o; o >>= 1) {
        if (threadIdx.x < o) sd[threadIdx.x] += sd[threadIdx.x + o];
        __syncthreads();
    }
    if (threadIdx.x == 0) {
        float vq = (float)(sd[0] / ((double)B_ROWS * (double)D_EMB));
        out[0] = vq;
        out[1] = 0.25f * vq;
    }
}

// ---------------- launch ----------------
extern "C" void kernel_launch(void* const* d_in, const int* in_sizes, int n_in,
                              void* d_out, int out_size) {
    const int*   node_type = (const int*)d_in[0];
    const float* z         = (const float*)d_in[1];
    const float* cb        = (const float*)d_in[2];
    float* out = (float*)d_out;

    cudaFuncSetAttribute(vq_mma_kernel,
                         cudaFuncAttributeMaxDynamicSharedMemorySize, SMEM_DYN);

    reset_kernel<<<1, 32>>>();
    classify_kernel<<<B_ROWS / 256, 256>>>(node_type);
    enorm_kernel<<<64, 256>>>(cb);
    dim3 grid(TILES_M, 4);
    vq_mma_kernel<<<grid, 256, SMEM_DYN>>>(z, cb, out);
    rowloss_reduce_kernel<<<256, 256>>>();
    finalize_kernel<<<1, 256>>>(out);
}

// round 16
// speedup vs baseline: 2.0708x; 2.0708x over previous
#include <cuda_runtime.h>
#include <math_constants.h>

#define B_ROWS   131072
#define D_EMB    256
#define QSIZE    128
#define TM       64
#define TILES_M  (B_ROWS / TM)   // 2048
#define MARGIN   1.5f
#define NPART2   (B_ROWS / 8)    // 16384 epilogue blocks

// ---------------- device scratch (static) ----------------
__device__ int    g_counts[4];
__device__ int    g_buckets[4 * B_ROWS];
__device__ float  g_enorm[512];
__device__ double g_bsum[NPART2];

// ---------------- classify + enorm fused (independent block ranges) ------
__global__ void prep_kernel(const int* __restrict__ node_type,
                            const float* __restrict__ cb) {
    if (blockIdx.x < 512) {
        // classify: block-aggregated bucket scatter
        __shared__ int s_cnt[4];
        __shared__ int s_base[4];
        int tid = threadIdx.x;
        int i = blockIdx.x * blockDim.x + tid;
        if (tid < 4) s_cnt[tid] = 0;
        __syncthreads();
        int t = node_type[i];
        int g = (t == 5) ? 0 : (t == 6) ? 1 : (t == 7) ? 2 : 3;
        int p = atomicAdd(&s_cnt[g], 1);
        __syncthreads();
        if (tid < 4) s_base[tid] = atomicAdd(&g_counts[tid], s_cnt[tid]);
        __syncthreads();
        g_buckets[g * B_ROWS + s_base[g] + p] = i;
    } else {
        // enorm: one warp per code
        int code = (blockIdx.x - 512) * 8 + (threadIdx.x >> 5);
        int lane = threadIdx.x & 31;
        const float* row = cb + (size_t)code * D_EMB;
        float s = 0.f;
        #pragma unroll
        for (int j = 0; j < 8; ++j)
            s = fmaf(row[lane + 32 * j], row[lane + 32 * j], s);
        #pragma unroll
        for (int o = 16; o; o >>= 1) s += __shfl_xor_sync(0xffffffffu, s, o);
        if (lane == 0) g_enorm[code] = s;
    }
}

// ---------------- PTX helpers ----------------
__device__ __forceinline__ unsigned smem_u32(const void* p) {
    unsigned a;
    asm("{ .reg .u64 t; cvta.to.shared.u64 t, %1; cvt.u32.u64 %0, t; }"
        : "=r"(a) : "l"(p));
    return a;
}
__device__ __forceinline__ void cp16(unsigned saddr, const void* gaddr) {
    asm volatile("cp.async.cg.shared.global [%0], [%1], 16;"
                 :: "r"(saddr), "l"(gaddr) : "memory");
}
__device__ __forceinline__ void cp_arrive(unsigned mbar) {
    asm volatile("cp.async.mbarrier.arrive.noinc.shared::cta.b64 [%0];"
                 :: "r"(mbar) : "memory");
}
__device__ __forceinline__ void mbar_init(unsigned a, unsigned c) {
    asm volatile("mbarrier.init.shared.b64 [%0], %1;" :: "r"(a), "r"(c) : "memory");
}
__device__ __forceinline__ void mbar_arrive(unsigned a) {
    asm volatile("mbarrier.arrive.shared.b64 _, [%0];" :: "r"(a) : "memory");
}
__device__ __forceinline__ void mbar_wait(unsigned a, unsigned parity) {
    asm volatile(
        "{\n\t.reg .pred P;\n\t"
        "WL_%=:\n\t"
        "mbarrier.try_wait.parity.acquire.cta.shared::cta.b64 P, [%0], %1, 0x989680;\n\t"
        "@P bra.uni WD_%=;\n\t"
        "bra.uni WL_%=;\n\t"
        "WD_%=:\n\t}"
        :: "r"(a), "r"(parity) : "memory");
}
__device__ __forceinline__ void ldsm4(unsigned& r0, unsigned& r1,
                                      unsigned& r2, unsigned& r3, unsigned addr) {
    asm volatile("ldmatrix.sync.aligned.m8n8.x4.shared.b16 {%0,%1,%2,%3}, [%4];"
                 : "=r"(r0), "=r"(r1), "=r"(r2), "=r"(r3) : "r"(addr));
}
__device__ __forceinline__ void mma_tf32(float* d, const unsigned* a,
                                         const unsigned* b) {
    asm volatile(
        "mma.sync.aligned.m16n8k8.row.col.f32.tf32.tf32.f32 "
        "{%0,%1,%2,%3}, {%4,%5,%6,%7}, {%8,%9}, {%0,%1,%2,%3};"
        : "+f"(d[0]), "+f"(d[1]), "+f"(d[2]), "+f"(d[3])
        : "r"(a[0]), "r"(a[1]), "r"(a[2]), "r"(a[3]), "r"(b[0]), "r"(b[1]));
}

// ---------------- smem layout ----------------
#define CHUNK_K   16
#define NCHUNK    16
#define NSTAGE    4
#define ROWF      20                       // 80B row stride: LDSM conflict-free
#define TA_BYTES  (TM * ROWF * 4)          // 5120
#define TB_BYTES  (128 * ROWF * 4)         // 10240
#define BUF_BYTES (TA_BYTES + TB_BYTES)    // 15360
#define OFF_BAR   (NSTAGE * BUF_BYTES)     // 61440: full[4] then empty[4]
#define OFF_ROWS  (OFF_BAR + 64)           // 64 int
#define OFF_EN    (OFF_ROWS + 256)         // 128 float
#define OFF_SEL   (OFF_EN + 512)           // 64 int
#define OFF_NC    (OFF_SEL + 256)          // 64 int
#define OFF_CAND  (OFF_NC + 256)           // 64*8 int
#define OFF_PMIN  (OFF_CAND + 2048)        // 128 float
#define OFF_PCOL  (OFF_PMIN + 512)         // 128 int
#define OFF_RMIN  (OFF_PCOL + 512)         // 64 float
#define OFF_WORK  (OFF_RMIN + 256)         // 64 int + counter
#define SMEM_DYN  (OFF_WORK + 272)         // ~66.7 KB -> 3 CTAs/SM

// ---------------- main kernel (identical to R14) ----------------
__global__ void __launch_bounds__(256, 3) vq_mma_kernel(
    const float* __restrict__ z, const float* __restrict__ cb,
    float* __restrict__ out)
{
    extern __shared__ char sm[];
    const int g   = blockIdx.y;
    const int tid = threadIdx.x;
    const int cnt   = g_counts[g];
    const int start = blockIdx.x * TM;
    if (start >= cnt) return;

    int*   s_rows = (int*)  (sm + OFF_ROWS);
    float* s_en   = (float*)(sm + OFF_EN);
    int*   s_sel  = (int*)  (sm + OFF_SEL);
    int*   s_nc   = (int*)  (sm + OFF_NC);
    int*   s_cand = (int*)  (sm + OFF_CAND);
    float* s_pmin = (float*)(sm + OFF_PMIN);
    int*   s_pcol = (int*)  (sm + OFF_PCOL);
    float* s_rmin = (float*)(sm + OFF_RMIN);
    int*   s_work = (int*)  (sm + OFF_WORK);
    int*   s_nwork = s_work + 64;

    const unsigned sb = smem_u32(sm);

    if (tid < TM) {
        int r = (start + tid < cnt) ? g_buckets[g * B_ROWS + start + tid] : -1;
        s_rows[tid] = r;
        s_nc[tid] = 0;
    }
    if (tid >= 128 && tid < 256) s_en[tid - 128] = g_enorm[g * QSIZE + tid - 128];
    if (tid == 0) {
        #pragma unroll
        for (int s = 0; s < NSTAGE; ++s) {
            mbar_init(sb + OFF_BAR + s * 8, 256);       // full: 256 cp-arrives
            mbar_init(sb + OFF_BAR + 32 + s * 8, 8);    // empty: 8 warp arrives
        }
        *s_nwork = 0;
    }
    __syncthreads();

    // ---- loader mapping: per chunk A = 1 seg/thread, B = 2 segs/thread ----
    const float* zsrc;  unsigned adst;
    const float* esrc0; unsigned bdst0;
    const float* esrc1; unsigned bdst1;
    {
        int row = tid >> 2, cs = tid & 3;
        int r = s_rows[row];
        zsrc = z + (size_t)(r < 0 ? 0 : r) * D_EMB + cs * 4;
        adst = (unsigned)(row * ROWF + cs * 4) * 4;
        int brow0 = tid >> 2,          bcs0 = tid & 3;
        int brow1 = (tid + 256) >> 2,  bcs1 = tid & 3;
        esrc0 = cb + (size_t)(g * QSIZE + brow0) * D_EMB + bcs0 * 4;
        esrc1 = cb + (size_t)(g * QSIZE + brow1) * D_EMB + bcs1 * 4;
        bdst0 = (unsigned)TA_BYTES + (unsigned)(brow0 * ROWF + bcs0 * 4) * 4;
        bdst1 = (unsigned)TA_BYTES + (unsigned)(brow1 * ROWF + bcs1 * 4) * 4;
    }

    // warp tiling: 4 warp-rows x 2 warp-cols; warp tile = 16 rows x 64 cols
    const int w = tid >> 5, lane = tid & 31;
    const int gq = lane >> 2, t = lane & 3;
    const int wm = w >> 1, wn = w & 1;
    const int R0 = wm * 16, CW = wn * 64;

    const int g8 = lane >> 3, rw = lane & 7;
    const unsigned aOff =
        (unsigned)((R0 + (g8 & 1) * 8 + rw) * ROWF + (g8 >> 1) * 4) * 4;
    unsigned bOff[4];
    #pragma unroll
    for (int p = 0; p < 4; ++p)
        bOff[p] = (unsigned)TA_BYTES +
            (unsigned)((CW + (2 * p + (g8 >> 1)) * 8 + rw) * ROWF + (g8 & 1) * 4) * 4;

    float acc[8][4];
    #pragma unroll
    for (int nf = 0; nf < 8; ++nf)
        #pragma unroll
        for (int q = 0; q < 4; ++q) acc[nf][q] = 0.f;

    // prologue: fill all 4 stages
    #pragma unroll
    for (int c0 = 0; c0 < NSTAGE; ++c0) {
        unsigned buf = sb + c0 * BUF_BYTES;
        cp16(buf + adst,  zsrc  + c0 * CHUNK_K);
        cp16(buf + bdst0, esrc0 + c0 * CHUNK_K);
        cp16(buf + bdst1, esrc1 + c0 * CHUNK_K);
        cp_arrive(sb + OFF_BAR + c0 * 8);
    }

    #pragma unroll 1
    for (int c = 0; c < NCHUNK; ++c) {
        const int s = c & 3, gen = c >> 2;
        mbar_wait(sb + OFF_BAR + s * 8, gen & 1);

        const unsigned bufb = sb + s * BUF_BYTES;
        #pragma unroll
        for (int ks = 0; ks < 2; ++ks) {
            unsigned a[4];
            ldsm4(a[0], a[1], a[2], a[3], bufb + aOff + ks * 32);
            unsigned b[8][2];
            #pragma unroll
            for (int p = 0; p < 4; ++p)
                ldsm4(b[2 * p][0], b[2 * p][1], b[2 * p + 1][0], b[2 * p + 1][1],
                      bufb + bOff[p] + ks * 32);
            #pragma unroll
            for (int nf = 0; nf < 8; ++nf)
                mma_tf32(acc[nf], a, b[nf]);
        }
        if (lane == 0) mbar_arrive(sb + OFF_BAR + 32 + s * 8);

        const int cn = c + NSTAGE;
        if (cn < NCHUNK) {
            mbar_wait(sb + OFF_BAR + 32 + s * 8, gen & 1);
            unsigned buf = sb + s * BUF_BYTES;
            cp16(buf + adst,  zsrc  + cn * CHUNK_K);
            cp16(buf + bdst0, esrc0 + cn * CHUNK_K);
            cp16(buf + bdst1, esrc1 + cn * CHUNK_K);
            cp_arrive(sb + OFF_BAR + s * 8);
        }
    }
    __syncthreads();

    // ---- per-warp partial argmin (score = en - 2*dot) ----
    #pragma unroll
    for (int h = 0; h < 2; ++h) {
        const int row = R0 + gq + h * 8;
        float v = CUDART_INF_F;  int cbest = 0x7fffffff;
        #pragma unroll
        for (int nf = 0; nf < 8; ++nf) {
            #pragma unroll
            for (int q = 0; q < 2; ++q) {
                int col = CW + nf * 8 + 2 * t + q;
                float s = fmaf(-2.f, acc[nf][h * 2 + q], s_en[col]);
                if (s < v || (s == v && col < cbest)) { v = s; cbest = col; }
            }
        }
        #pragma unroll
        for (int off = 1; off < 4; off <<= 1) {
            float v2 = __shfl_xor_sync(0xffffffffu, v, off);
            int   c2 = __shfl_xor_sync(0xffffffffu, cbest, off);
            if (v2 < v || (v2 == v && c2 < cbest)) { v = v2; cbest = c2; }
        }
        if (t == 0) {
            s_pmin[row * 2 + wn] = v;
            s_pcol[row * 2 + wn] = cbest;
        }
    }
    __syncthreads();

    if (tid < TM) {
        float v0 = s_pmin[tid * 2], v1 = s_pmin[tid * 2 + 1];
        int   c0 = s_pcol[tid * 2], c1 = s_pcol[tid * 2 + 1];
        bool take1 = (v1 < v0) || (v1 == v0 && c1 < c0);
        s_rmin[tid] = take1 ? v1 : v0;
        s_sel[tid]  = take1 ? c1 : c0;
    }
    __syncthreads();

    // ---- candidate collection within MARGIN of row min ----
    #pragma unroll
    for (int h = 0; h < 2; ++h) {
        const int row = R0 + gq + h * 8;
        const float thr = s_rmin[row] + MARGIN;
        #pragma unroll
        for (int nf = 0; nf < 8; ++nf) {
            #pragma unroll
            for (int q = 0; q < 2; ++q) {
                int col = CW + nf * 8 + 2 * t + q;
                float s = fmaf(-2.f, acc[nf][h * 2 + q], s_en[col]);
                if (s <= thr) {
                    int p = atomicAdd(&s_nc[row], 1);
                    if (p < 8) s_cand[row * 8 + p] = col;
                }
            }
        }
    }
    __syncthreads();

    // worklist of ambiguous rows
    if (tid < TM) {
        if (s_rows[tid] >= 0 && s_nc[tid] > 1) {
            int p = atomicAdd(s_nwork, 1);
            s_work[p] = tid;
        }
    }
    __syncthreads();

    // pooled exact fp32 rescue: 8 warps strip-mine the worklist
    const int nwork = *s_nwork;
    for (int wi = w; wi < nwork; wi += 8) {
        const int m = s_work[wi];
        const int nc = s_nc[m];
        const int r  = s_rows[m];
        const float* zr = z + (size_t)r * D_EMB;
        float zn = 0.f;
        #pragma unroll
        for (int j = 0; j < 8; ++j)
            zn = fmaf(zr[lane + 32 * j], zr[lane + 32 * j], zn);
        #pragma unroll
        for (int off = 16; off; off >>= 1)
            zn += __shfl_xor_sync(0xffffffffu, zn, off);
        float bestv = CUDART_INF_F;  int bestc = 0x7fffffff;
        int nit = (nc <= 8) ? nc : QSIZE;
        for (int i = 0; i < nit; ++i) {
            int col = (nc <= 8) ? s_cand[m * 8 + i] : i;
            const float* er = cb + (size_t)(g * QSIZE + col) * D_EMB;
            float p = 0.f;
            #pragma unroll
            for (int j = 0; j < 8; ++j)
                p = fmaf(zr[lane + 32 * j], er[lane + 32 * j], p);
            #pragma unroll
            for (int off = 16; off; off >>= 1)
                p += __shfl_xor_sync(0xffffffffu, p, off);
            float sc = fmaf(-2.f, p, zn + s_en[col]);
            if (sc < bestv || (sc == bestv && col < bestc)) { bestv = sc; bestc = col; }
        }
        if (lane == 0) s_sel[m] = bestc;
    }
    __syncthreads();

    if (tid < TM) {
        int r = s_rows[tid];
        if (r >= 0) out[2 + r] = (float)(g * QSIZE + s_sel[tid]);
    }
}

// ---- epilogue: st = z + (q - z); per-BLOCK deterministic loss partial ----
__global__ void __launch_bounds__(256) epilogue_kernel(
    const float* __restrict__ z, const float* __restrict__ cb,
    float* __restrict__ out)
{
    __shared__ float s_w[8];
    const int w = threadIdx.x >> 5, lane = threadIdx.x & 31;
    const int r = blockIdx.x * 8 + w;
    const int code = (int)out[2 + r];
    const float* zr = z  + (size_t)r * D_EMB;
    const float* qr = cb + (size_t)code * D_EMB;
    float* so = out + 2 + B_ROWS + (size_t)r * D_EMB;
    float lsum = 0.f;
    #pragma unroll
    for (int j = 0; j < 2; ++j) {
        int cc = lane * 4 + j * 128;
        float4 zv = *(const float4*)(zr + cc);
        float4 qv = *(const float4*)(qr + cc);
        float dx = qv.x - zv.x, dy = qv.y - zv.y;
        float dz = qv.z - zv.z, dw = qv.w - zv.w;
        *(float2*)(so + cc)     = make_float2(zv.x + dx, zv.y + dy);
        *(float2*)(so + cc + 2) = make_float2(zv.z + dz, zv.w + dw);
        lsum += dx * dx; lsum += dy * dy; lsum += dz * dz; lsum += dw * dw;
    }
    #pragma unroll
    for (int off = 16; off; off >>= 1)
        lsum += __shfl_xor_sync(0xffffffffu, lsum, off);
    if (lane == 0) s_w[w] = lsum;
    __syncthreads();
    if (threadIdx.x == 0) {
        double s = 0.0;
        #pragma unroll
        for (int k = 0; k < 8; ++k) s += (double)s_w[k];   // fixed order
        g_bsum[blockIdx.x] = s;
    }
}

__global__ void finalize_kernel(float* __restrict__ out) {
    __shared__ double sd[256];
    double s = 0.0;
    for (int i = threadIdx.x; i < NPART2; i += 256) s += g_bsum[i];  // fixed stride
    sd[threadIdx.x] = s;
    __syncthreads();
    #pragma unroll
    for (int o = 128; o; o >>= 1) {
        if (threadIdx.x < o) sd[threadIdx.x] += sd[threadIdx.x + o];
        __syncthreads();
    }
    if (threadIdx.x == 0) {
        float vq = (float)(sd[0] / ((double)B_ROWS * (double)D_EMB));
        out[0] = vq;
        out[1] = 0.25f * vq;
    }
}

// ---------------- launch ----------------
extern "C" void kernel_launch(void* const* d_in, const int* in_sizes, int n_in,
                              void* d_out, int out_size) {
    const int*   node_type = (const int*)d_in[0];
    const float* z         = (const float*)d_in[1];
    const float* cb        = (const float*)d_in[2];
    float* out = (float*)d_out;

    cudaFuncSetAttribute(vq_mma_kernel,
                         cudaFuncAttributeMaxDynamicSharedMemorySize, SMEM_DYN);

    void* counts_ptr = nullptr;
    cudaGetSymbolAddress(&counts_ptr, g_counts);
    cudaMemsetAsync(counts_ptr, 0, 4 * sizeof(int));

    prep_kernel<<<576, 256>>>(node_type, cb);
    dim3 grid(TILES_M, 4);
    vq_mma_kernel<<<grid, 256, SMEM_DYN>>>(z, cb, out);
    epilogue_kernel<<<B_ROWS / 8, 256>>>(z, cb, out);
    finalize_kernel<<<1, 256>>>(out);
}

// round 17
// speedup vs baseline: 2.1015x; 1.0148x over previous
#include <cuda_runtime.h>
#include <math_constants.h>

#define B_ROWS   131072
#define D_EMB    256
#define QSIZE    128
#define TM       64
#define TILES_M  (B_ROWS / TM)   // 2048
#define MARGIN   1.5f
#define NPART2   (B_ROWS / 8)    // 16384 epilogue blocks

// ---------------- device scratch (static) ----------------
__device__ int    g_counts[4];
__device__ int    g_buckets[4 * B_ROWS];
__device__ float  g_enorm[512];
__device__ double g_bsum[NPART2];
__device__ double g_bsum2[64];

// ---------------- classify + enorm fused (independent block ranges) ------
__global__ void prep_kernel(const int* __restrict__ node_type,
                            const float* __restrict__ cb) {
    if (blockIdx.x < 512) {
        __shared__ int s_cnt[4];
        __shared__ int s_base[4];
        int tid = threadIdx.x;
        int i = blockIdx.x * blockDim.x + tid;
        if (tid < 4) s_cnt[tid] = 0;
        __syncthreads();
        int t = node_type[i];
        int g = (t == 5) ? 0 : (t == 6) ? 1 : (t == 7) ? 2 : 3;
        int p = atomicAdd(&s_cnt[g], 1);
        __syncthreads();
        if (tid < 4) s_base[tid] = atomicAdd(&g_counts[tid], s_cnt[tid]);
        __syncthreads();
        g_buckets[g * B_ROWS + s_base[g] + p] = i;
    } else {
        int code = (blockIdx.x - 512) * 8 + (threadIdx.x >> 5);
        int lane = threadIdx.x & 31;
        const float* row = cb + (size_t)code * D_EMB;
        float s = 0.f;
        #pragma unroll
        for (int j = 0; j < 8; ++j)
            s = fmaf(row[lane + 32 * j], row[lane + 32 * j], s);
        #pragma unroll
        for (int o = 16; o; o >>= 1) s += __shfl_xor_sync(0xffffffffu, s, o);
        if (lane == 0) g_enorm[code] = s;
    }
}

// ---------------- PTX helpers ----------------
__device__ __forceinline__ unsigned smem_u32(const void* p) {
    unsigned a;
    asm("{ .reg .u64 t; cvta.to.shared.u64 t, %1; cvt.u32.u64 %0, t; }"
        : "=r"(a) : "l"(p));
    return a;
}
__device__ __forceinline__ void cp16(unsigned saddr, const void* gaddr) {
    asm volatile("cp.async.cg.shared.global [%0], [%1], 16;"
                 :: "r"(saddr), "l"(gaddr) : "memory");
}
__device__ __forceinline__ void cp_arrive(unsigned mbar) {
    asm volatile("cp.async.mbarrier.arrive.noinc.shared::cta.b64 [%0];"
                 :: "r"(mbar) : "memory");
}
__device__ __forceinline__ void mbar_init(unsigned a, unsigned c) {
    asm volatile("mbarrier.init.shared.b64 [%0], %1;" :: "r"(a), "r"(c) : "memory");
}
__device__ __forceinline__ void mbar_arrive(unsigned a) {
    asm volatile("mbarrier.arrive.shared.b64 _, [%0];" :: "r"(a) : "memory");
}
__device__ __forceinline__ void mbar_wait(unsigned a, unsigned parity) {
    asm volatile(
        "{\n\t.reg .pred P;\n\t"
        "WL_%=:\n\t"
        "mbarrier.try_wait.parity.acquire.cta.shared::cta.b64 P, [%0], %1, 0x989680;\n\t"
        "@P bra.uni WD_%=;\n\t"
        "bra.uni WL_%=;\n\t"
        "WD_%=:\n\t}"
        :: "r"(a), "r"(parity) : "memory");
}
__device__ __forceinline__ void ldsm4(unsigned& r0, unsigned& r1,
                                      unsigned& r2, unsigned& r3, unsigned addr) {
    asm volatile("ldmatrix.sync.aligned.m8n8.x4.shared.b16 {%0,%1,%2,%3}, [%4];"
                 : "=r"(r0), "=r"(r1), "=r"(r2), "=r"(r3) : "r"(addr));
}
__device__ __forceinline__ void mma_tf32(float* d, const unsigned* a,
                                         const unsigned* b) {
    asm volatile(
        "mma.sync.aligned.m16n8k8.row.col.f32.tf32.tf32.f32 "
        "{%0,%1,%2,%3}, {%4,%5,%6,%7}, {%8,%9}, {%0,%1,%2,%3};"
        : "+f"(d[0]), "+f"(d[1]), "+f"(d[2]), "+f"(d[3])
        : "r"(a[0]), "r"(a[1]), "r"(a[2]), "r"(a[3]), "r"(b[0]), "r"(b[1]));
}

// ---------------- smem layout ----------------
#define CHUNK_K   16
#define NCHUNK    16
#define NSTAGE    4
#define ROWF      20                       // 80B row stride: LDSM conflict-free
#define TA_BYTES  (TM * ROWF * 4)          // 5120
#define TB_BYTES  (128 * ROWF * 4)         // 10240
#define BUF_BYTES (TA_BYTES + TB_BYTES)    // 15360
#define OFF_BAR   (NSTAGE * BUF_BYTES)     // 61440: full[4] then empty[4]
#define OFF_ROWS  (OFF_BAR + 64)           // 64 int
#define OFF_EN    (OFF_ROWS + 256)         // 128 float
#define OFF_SEL   (OFF_EN + 512)           // 64 int
#define OFF_NC    (OFF_SEL + 256)          // 64 int
#define OFF_CAND  (OFF_NC + 256)           // 64*8 int
#define OFF_PMIN  (OFF_CAND + 2048)        // 128 float
#define OFF_PCOL  (OFF_PMIN + 512)         // 128 int
#define OFF_RMIN  (OFF_PCOL + 512)         // 64 float
#define OFF_WORK  (OFF_RMIN + 256)         // 64 int + counter
#define SMEM_DYN  (OFF_WORK + 272)         // ~66.7 KB -> 3 CTAs/SM

// ---------------- main kernel (identical to R14) ----------------
__global__ void __launch_bounds__(256, 3) vq_mma_kernel(
    const float* __restrict__ z, const float* __restrict__ cb,
    float* __restrict__ out)
{
    extern __shared__ char sm[];
    const int g   = blockIdx.y;
    const int tid = threadIdx.x;
    const int cnt   = g_counts[g];
    const int start = blockIdx.x * TM;
    if (start >= cnt) return;

    int*   s_rows = (int*)  (sm + OFF_ROWS);
    float* s_en   = (float*)(sm + OFF_EN);
    int*   s_sel  = (int*)  (sm + OFF_SEL);
    int*   s_nc   = (int*)  (sm + OFF_NC);
    int*   s_cand = (int*)  (sm + OFF_CAND);
    float* s_pmin = (float*)(sm + OFF_PMIN);
    int*   s_pcol = (int*)  (sm + OFF_PCOL);
    float* s_rmin = (float*)(sm + OFF_RMIN);
    int*   s_work = (int*)  (sm + OFF_WORK);
    int*   s_nwork = s_work + 64;

    const unsigned sb = smem_u32(sm);

    if (tid < TM) {
        int r = (start + tid < cnt) ? g_buckets[g * B_ROWS + start + tid] : -1;
        s_rows[tid] = r;
        s_nc[tid] = 0;
    }
    if (tid >= 128 && tid < 256) s_en[tid - 128] = g_enorm[g * QSIZE + tid - 128];
    if (tid == 0) {
        #pragma unroll
        for (int s = 0; s < NSTAGE; ++s) {
            mbar_init(sb + OFF_BAR + s * 8, 256);
            mbar_init(sb + OFF_BAR + 32 + s * 8, 8);
        }
        *s_nwork = 0;
    }
    __syncthreads();

    const float* zsrc;  unsigned adst;
    const float* esrc0; unsigned bdst0;
    const float* esrc1; unsigned bdst1;
    {
        int row = tid >> 2, cs = tid & 3;
        int r = s_rows[row];
        zsrc = z + (size_t)(r < 0 ? 0 : r) * D_EMB + cs * 4;
        adst = (unsigned)(row * ROWF + cs * 4) * 4;
        int brow0 = tid >> 2,          bcs0 = tid & 3;
        int brow1 = (tid + 256) >> 2,  bcs1 = tid & 3;
        esrc0 = cb + (size_t)(g * QSIZE + brow0) * D_EMB + bcs0 * 4;
        esrc1 = cb + (size_t)(g * QSIZE + brow1) * D_EMB + bcs1 * 4;
        bdst0 = (unsigned)TA_BYTES + (unsigned)(brow0 * ROWF + bcs0 * 4) * 4;
        bdst1 = (unsigned)TA_BYTES + (unsigned)(brow1 * ROWF + bcs1 * 4) * 4;
    }

    const int w = tid >> 5, lane = tid & 31;
    const int gq = lane >> 2, t = lane & 3;
    const int wm = w >> 1, wn = w & 1;
    const int R0 = wm * 16, CW = wn * 64;

    const int g8 = lane >> 3, rw = lane & 7;
    const unsigned aOff =
        (unsigned)((R0 + (g8 & 1) * 8 + rw) * ROWF + (g8 >> 1) * 4) * 4;
    unsigned bOff[4];
    #pragma unroll
    for (int p = 0; p < 4; ++p)
        bOff[p] = (unsigned)TA_BYTES +
            (unsigned)((CW + (2 * p + (g8 >> 1)) * 8 + rw) * ROWF + (g8 & 1) * 4) * 4;

    float acc[8][4];
    #pragma unroll
    for (int nf = 0; nf < 8; ++nf)
        #pragma unroll
        for (int q = 0; q < 4; ++q) acc[nf][q] = 0.f;

    #pragma unroll
    for (int c0 = 0; c0 < NSTAGE; ++c0) {
        unsigned buf = sb + c0 * BUF_BYTES;
        cp16(buf + adst,  zsrc  + c0 * CHUNK_K);
        cp16(buf + bdst0, esrc0 + c0 * CHUNK_K);
        cp16(buf + bdst1, esrc1 + c0 * CHUNK_K);
        cp_arrive(sb + OFF_BAR + c0 * 8);
    }

    #pragma unroll 1
    for (int c = 0; c < NCHUNK; ++c) {
        const int s = c & 3, gen = c >> 2;
        mbar_wait(sb + OFF_BAR + s * 8, gen & 1);

        const unsigned bufb = sb + s * BUF_BYTES;
        #pragma unroll
        for (int ks = 0; ks < 2; ++ks) {
            unsigned a[4];
            ldsm4(a[0], a[1], a[2], a[3], bufb + aOff + ks * 32);
            unsigned b[8][2];
            #pragma unroll
            for (int p = 0; p < 4; ++p)
                ldsm4(b[2 * p][0], b[2 * p][1], b[2 * p + 1][0], b[2 * p + 1][1],
                      bufb + bOff[p] + ks * 32);
            #pragma unroll
            for (int nf = 0; nf < 8; ++nf)
                mma_tf32(acc[nf], a, b[nf]);
        }
        if (lane == 0) mbar_arrive(sb + OFF_BAR + 32 + s * 8);

        const int cn = c + NSTAGE;
        if (cn < NCHUNK) {
            mbar_wait(sb + OFF_BAR + 32 + s * 8, gen & 1);
            unsigned buf = sb + s * BUF_BYTES;
            cp16(buf + adst,  zsrc  + cn * CHUNK_K);
            cp16(buf + bdst0, esrc0 + cn * CHUNK_K);
            cp16(buf + bdst1, esrc1 + cn * CHUNK_K);
            cp_arrive(sb + OFF_BAR + s * 8);
        }
    }
    __syncthreads();

    #pragma unroll
    for (int h = 0; h < 2; ++h) {
        const int row = R0 + gq + h * 8;
        float v = CUDART_INF_F;  int cbest = 0x7fffffff;
        #pragma unroll
        for (int nf = 0; nf < 8; ++nf) {
            #pragma unroll
            for (int q = 0; q < 2; ++q) {
                int col = CW + nf * 8 + 2 * t + q;
                float s = fmaf(-2.f, acc[nf][h * 2 + q], s_en[col]);
                if (s < v || (s == v && col < cbest)) { v = s; cbest = col; }
            }
        }
        #pragma unroll
        for (int off = 1; off < 4; off <<= 1) {
            float v2 = __shfl_xor_sync(0xffffffffu, v, off);
            int   c2 = __shfl_xor_sync(0xffffffffu, cbest, off);
            if (v2 < v || (v2 == v && c2 < cbest)) { v = v2; cbest = c2; }
        }
        if (t == 0) {
            s_pmin[row * 2 + wn] = v;
            s_pcol[row * 2 + wn] = cbest;
        }
    }
    __syncthreads();

    if (tid < TM) {
        float v0 = s_pmin[tid * 2], v1 = s_pmin[tid * 2 + 1];
        int   c0 = s_pcol[tid * 2], c1 = s_pcol[tid * 2 + 1];
        bool take1 = (v1 < v0) || (v1 == v0 && c1 < c0);
        s_rmin[tid] = take1 ? v1 : v0;
        s_sel[tid]  = take1 ? c1 : c0;
    }
    __syncthreads();

    #pragma unroll
    for (int h = 0; h < 2; ++h) {
        const int row = R0 + gq + h * 8;
        const float thr = s_rmin[row] + MARGIN;
        #pragma unroll
        for (int nf = 0; nf < 8; ++nf) {
            #pragma unroll
            for (int q = 0; q < 2; ++q) {
                int col = CW + nf * 8 + 2 * t + q;
                float s = fmaf(-2.f, acc[nf][h * 2 + q], s_en[col]);
                if (s <= thr) {
                    int p = atomicAdd(&s_nc[row], 1);
                    if (p < 8) s_cand[row * 8 + p] = col;
                }
            }
        }
    }
    __syncthreads();

    if (tid < TM) {
        if (s_rows[tid] >= 0 && s_nc[tid] > 1) {
            int p = atomicAdd(s_nwork, 1);
            s_work[p] = tid;
        }
    }
    __syncthreads();

    const int nwork = *s_nwork;
    for (int wi = w; wi < nwork; wi += 8) {
        const int m = s_work[wi];
        const int nc = s_nc[m];
        const int r  = s_rows[m];
        const float* zr = z + (size_t)r * D_EMB;
        float zn = 0.f;
        #pragma unroll
        for (int j = 0; j < 8; ++j)
            zn = fmaf(zr[lane + 32 * j], zr[lane + 32 * j], zn);
        #pragma unroll
        for (int off = 16; off; off >>= 1)
            zn += __shfl_xor_sync(0xffffffffu, zn, off);
        float bestv = CUDART_INF_F;  int bestc = 0x7fffffff;
        int nit = (nc <= 8) ? nc : QSIZE;
        for (int i = 0; i < nit; ++i) {
            int col = (nc <= 8) ? s_cand[m * 8 + i] : i;
            const float* er = cb + (size_t)(g * QSIZE + col) * D_EMB;
            float p = 0.f;
            #pragma unroll
            for (int j = 0; j < 8; ++j)
                p = fmaf(zr[lane + 32 * j], er[lane + 32 * j], p);
            #pragma unroll
            for (int off = 16; off; off >>= 1)
                p += __shfl_xor_sync(0xffffffffu, p, off);
            float sc = fmaf(-2.f, p, zn + s_en[col]);
            if (sc < bestv || (sc == bestv && col < bestc)) { bestv = sc; bestc = col; }
        }
        if (lane == 0) s_sel[m] = bestc;
    }
    __syncthreads();

    if (tid < TM) {
        int r = s_rows[tid];
        if (r >= 0) out[2 + r] = (float)(g * QSIZE + s_sel[tid]);
    }
}

// ---- epilogue: st = z + (q - z); per-BLOCK deterministic loss partial ----
__global__ void __launch_bounds__(256) epilogue_kernel(
    const float* __restrict__ z, const float* __restrict__ cb,
    float* __restrict__ out)
{
    __shared__ float s_w[8];
    const int w = threadIdx.x >> 5, lane = threadIdx.x & 31;
    const int r = blockIdx.x * 8 + w;
    const int code = (int)out[2 + r];
    const float* zr = z  + (size_t)r * D_EMB;
    const float* qr = cb + (size_t)code * D_EMB;
    float* so = out + 2 + B_ROWS + (size_t)r * D_EMB;
    float lsum = 0.f;
    #pragma unroll
    for (int j = 0; j < 2; ++j) {
        int cc = lane * 4 + j * 128;
        float4 zv = *(const float4*)(zr + cc);
        float4 qv = *(const float4*)(qr + cc);
        float dx = qv.x - zv.x, dy = qv.y - zv.y;
        float dz = qv.z - zv.z, dw = qv.w - zv.w;
        *(float2*)(so + cc)     = make_float2(zv.x + dx, zv.y + dy);
        *(float2*)(so + cc + 2) = make_float2(zv.z + dz, zv.w + dw);
        lsum += dx * dx; lsum += dy * dy; lsum += dz * dz; lsum += dw * dw;
    }
    #pragma unroll
    for (int off = 16; off; off >>= 1)
        lsum += __shfl_xor_sync(0xffffffffu, lsum, off);
    if (lane == 0) s_w[w] = lsum;
    __syncthreads();
    if (threadIdx.x == 0) {
        double s = 0.0;
        #pragma unroll
        for (int k = 0; k < 8; ++k) s += (double)s_w[k];   // fixed order
        g_bsum[blockIdx.x] = s;
    }
}

// ---- two-level deterministic loss reduction ----
__global__ void __launch_bounds__(256) reduce2_kernel() {
    __shared__ double sd[256];
    int base = blockIdx.x * 256;
    sd[threadIdx.x] = g_bsum[base + threadIdx.x];
    __syncthreads();
    #pragma unroll
    for (int o = 128; o; o >>= 1) {
        if (threadIdx.x < o) sd[threadIdx.x] += sd[threadIdx.x + o];
        __syncthreads();
    }
    if (threadIdx.x == 0) g_bsum2[blockIdx.x] = sd[0];
}

__global__ void finalize_kernel(float* __restrict__ out) {
    if (threadIdx.x == 0) {
        double s = 0.0;
        #pragma unroll
        for (int i = 0; i < 64; ++i) s += g_bsum2[i];     // fixed order
        float vq = (float)(s / ((double)B_ROWS * (double)D_EMB));
        out[0] = vq;
        out[1] = 0.25f * vq;
    }
}

// ---------------- launch ----------------
extern "C" void kernel_launch(void* const* d_in, const int* in_sizes, int n_in,
                              void* d_out, int out_size) {
    const int*   node_type = (const int*)d_in[0];
    const float* z         = (const float*)d_in[1];
    const float* cb        = (const float*)d_in[2];
    float* out = (float*)d_out;

    cudaFuncSetAttribute(vq_mma_kernel,
                         cudaFuncAttributeMaxDynamicSharedMemorySize, SMEM_DYN);

    void* counts_ptr = nullptr;
    cudaGetSymbolAddress(&counts_ptr, g_counts);
    cudaMemsetAsync(counts_ptr, 0, 4 * sizeof(int));

    prep_kernel<<<576, 256>>>(node_type, cb);
    dim3 grid(TILES_M, 4);
    vq_mma_kernel<<<grid, 256, SMEM_DYN>>>(z, cb, out);
    epilogue_kernel<<<B_ROWS / 8, 256>>>(z, cb, out);
    reduce2_kernel<<<64, 256>>>();
    finalize_kernel<<<1, 32>>>(out);
}